// round 1
// baseline (speedup 1.0000x reference)
#include <cuda_runtime.h>
#include <math.h>

#define S_DIM 512
#define B_DIM 32
#define T_DIM 1024
#define E_DIM 512
#define Q_DIM 128
#define SPB   8          // s-rows per block in kernel C
#define CUT   16.0f      // exponent cutoff: exp(-16) ~ 1.1e-7

// Scratch (allocation-free rule: __device__ globals). Layout [B][S].
__device__ float g_mr[B_DIM * S_DIM];    // mean_raw = exp(q.w0 + b0)
__device__ float g_sd[B_DIM * S_DIM];    // std      = exp(q.w1 + b1)
__device__ float g_mean[B_DIM * S_DIM];  // position + cumsum(mean_raw)/20

// ---------------------------------------------------------------------------
// Kernel A: one warp per (s,b). Two length-128 dot products + exp.
// ---------------------------------------------------------------------------
__global__ void ga_qdot(const float* __restrict__ q,
                        const float* __restrict__ W,
                        const float* __restrict__ bias) {
    int gwarp = (blockIdx.x * blockDim.x + threadIdx.x) >> 5;
    int lane  = threadIdx.x & 31;
    if (gwarp >= S_DIM * B_DIM) return;
    int s = gwarp / B_DIM;
    int b = gwarp % B_DIM;

    const float4* qr = (const float4*)(q + ((size_t)s * B_DIM + b) * Q_DIM);
    const float4* w0 = (const float4*)(W);
    const float4* w1 = (const float4*)(W + Q_DIM);

    float4 qv = qr[lane];
    float4 a0 = w0[lane];
    float4 a1 = w1[lane];
    float d0 = qv.x * a0.x + qv.y * a0.y + qv.z * a0.z + qv.w * a0.w;
    float d1 = qv.x * a1.x + qv.y * a1.y + qv.z * a1.z + qv.w * a1.w;

    #pragma unroll
    for (int off = 16; off > 0; off >>= 1) {
        d0 += __shfl_xor_sync(0xFFFFFFFFu, d0, off);
        d1 += __shfl_xor_sync(0xFFFFFFFFu, d1, off);
    }
    if (lane == 0) {
        g_mr[b * S_DIM + s] = expf(d0 + bias[0]);
        g_sd[b * S_DIM + s] = expf(d1 + bias[1]);
    }
}

// ---------------------------------------------------------------------------
// Kernel B: one block per b, 512-thread inclusive scan over S.
// mean = position + cumsum(mean_raw)/20. Also written to output mean slot.
// ---------------------------------------------------------------------------
__global__ void ga_scan(const float* __restrict__ pos,
                        float* __restrict__ out_mean) {
    int b = blockIdx.x;
    int s = threadIdx.x;  // 512 threads
    __shared__ float sh[S_DIM];

    sh[s] = g_mr[b * S_DIM + s];
    __syncthreads();
    #pragma unroll
    for (int off = 1; off < S_DIM; off <<= 1) {
        float x = (s >= off) ? sh[s - off] : 0.0f;
        __syncthreads();
        sh[s] += x;
        __syncthreads();
    }
    float m = pos[s * B_DIM + b] + sh[s] * (1.0f / 20.0f);
    g_mean[b * S_DIM + s]   = m;
    out_mean[s * B_DIM + b] = m;
}

// ---------------------------------------------------------------------------
// Kernel C: windowed Gaussian attention.
// Block = (s-chunk of SPB rows, batch b). 128 threads: thread t handles
// E elements [4t, 4t+4). Weights (incl. mask) computed once per (s,t) into
// shared, then broadcast to all 128 threads during the FMA loop.
// ---------------------------------------------------------------------------
__global__ void __launch_bounds__(128) ga_ctx(const float* __restrict__ emb,
                                              const float* __restrict__ mask,
                                              float* __restrict__ out) {
    int b   = blockIdx.y;
    int s0  = blockIdx.x * SPB;
    int tid = threadIdx.x;

    __shared__ float smean[SPB];
    __shared__ float sstd[SPB];
    __shared__ float sw[128];

    if (tid < SPB) {
        smean[tid] = g_mean[b * S_DIM + s0 + tid];
        sstd[tid]  = g_sd[b * S_DIM + s0 + tid];
    }
    __syncthreads();

    for (int i = 0; i < SPB; i++) {
        float mean = smean[i];
        float stdv = sstd[i];
        float hw   = sqrtf(CUT / stdv);
        // Uniform across block (all inputs from shared). Clamp in float
        // before int cast so inf/huge values stay defined.
        int tlo = (int)fmaxf(0.0f, ceilf(mean - hw));
        int thi = (int)fminf((float)(T_DIM - 1), floorf(mean + hw));

        float4 acc = make_float4(0.0f, 0.0f, 0.0f, 0.0f);

        for (int tb = tlo; tb <= thi; tb += 128) {
            int n = min(128, thi - tb + 1);
            __syncthreads();
            if (tid < n) {
                int   t = tb + tid;
                float d = mean - (float)t;
                sw[tid] = __expf(-stdv * d * d) * mask[t * B_DIM + b];
            }
            __syncthreads();

            const float* ep = emb + ((size_t)tb * B_DIM + b) * E_DIM + tid * 4;
            #pragma unroll 4
            for (int j = 0; j < n; j++) {
                float  w = sw[j];
                float4 v = *(const float4*)ep;
                acc.x += w * v.x;
                acc.y += w * v.y;
                acc.z += w * v.z;
                acc.w += w * v.w;
                ep += (size_t)B_DIM * E_DIM;
            }
        }

        *(float4*)(out + ((size_t)(s0 + i) * B_DIM + b) * E_DIM + tid * 4) = acc;
    }
}

// ---------------------------------------------------------------------------
extern "C" void kernel_launch(void* const* d_in, const int* in_sizes, int n_in,
                              void* d_out, int out_size) {
    const float* query = (const float*)d_in[0];  // [S,B,Q]
    const float* emb   = (const float*)d_in[1];  // [T,B,E]
    const float* mask  = (const float*)d_in[2];  // [T,B]
    const float* pos   = (const float*)d_in[3];  // [S,B]
    const float* W     = (const float*)d_in[4];  // [2,Q]
    const float* bias  = (const float*)d_in[5];  // [2]

    float* out_ctx  = (float*)d_out;                                  // [S,B,E]
    float* out_mean = (float*)d_out + (size_t)S_DIM * B_DIM * E_DIM;  // [S,B]

    // A: 16384 warps, 8 warps/block
    ga_qdot<<<(S_DIM * B_DIM) / 8, 256>>>(query, W, bias);
    // B: one block per batch
    ga_scan<<<B_DIM, S_DIM>>>(pos, out_mean);
    // C: (S/SPB, B) blocks of 128 threads
    dim3 grid(S_DIM / SPB, B_DIM);
    ga_ctx<<<grid, 128>>>(emb, mask, out_ctx);
}